// round 1
// baseline (speedup 1.0000x reference)
#include <cuda_runtime.h>
#include <cstdint>

#define NUM_USER   4096
#define NUM_ITEM   16384
#define NUM_HIDDEN 64
#define BATCH      1024
#define SETLEN     50
#define NJ         (BATCH * SETLEN)          // 51200 scatter updates

#define HASH_BITS  18
#define HASH_SIZE  (1u << HASH_BITS)         // 262144 slots, load factor ~0.2
#define HASH_MASK  (HASH_SIZE - 1u)
#define IDX_MASK   0x1FFFFull                // linear idx fits in 17 bits (51200 < 131072)

// Scratch: static device arrays (no allocation allowed in kernel_launch).
__device__ unsigned long long g_hash[HASH_SIZE];
__device__ unsigned int       g_nnz;

__device__ __forceinline__ unsigned int hash_cell(unsigned int c) {
    c *= 2654435761u;                        // Knuth multiplicative
    return (c >> 8) & HASH_MASK;
}

// ---------------------------------------------------------------------------
// 1) Clear hash table + nnz counter
// ---------------------------------------------------------------------------
__global__ void clear_kernel() {
    unsigned int i = blockIdx.x * blockDim.x + threadIdx.x;
    if (i < HASH_SIZE) g_hash[i] = 0ull;
    if (i == 0) g_nnz = 0u;
}

// ---------------------------------------------------------------------------
// 2) Insert all (cell, linear_idx) pairs. For duplicate cells, atomicMax keeps
//    the LARGEST linear index (== last-write-wins in (b,l) row-major order,
//    matching XLA CPU scatter semantics). First successful CAS into an empty
//    slot counts one unique cell -> sum(mask).
// ---------------------------------------------------------------------------
__global__ void insert_kernel(const int* __restrict__ idx_user,
                              const int* __restrict__ item_sets) {
    int j = blockIdx.x * blockDim.x + threadIdx.x;
    if (j >= NJ) return;
    int b = j / SETLEN;
    unsigned int u    = (unsigned int)idx_user[b];
    unsigned int it   = (unsigned int)item_sets[j];
    unsigned int cell = u * NUM_ITEM + it;

    unsigned long long keyhi = ((unsigned long long)(cell + 1u)) << 17;
    unsigned long long val   = keyhi | (unsigned long long)(unsigned int)j;

    unsigned int h = hash_cell(cell);
    while (true) {
        unsigned long long cur = g_hash[h];
        if (cur == 0ull) {
            unsigned long long old = atomicCAS(&g_hash[h], 0ull, val);
            if (old == 0ull) {               // claimed empty slot: first occurrence
                atomicAdd(&g_nnz, 1u);
                break;
            }
            cur = old;
        }
        if ((cur & ~IDX_MASK) == keyhi) {    // same key: keep max linear idx
            atomicMax(&g_hash[h], val);
            break;
        }
        h = (h + 1u) & HASH_MASK;            // different key: linear probe
    }
}

// ---------------------------------------------------------------------------
// 3) Resolve winners and scatter. Only the winning update per unique cell
//    computes the 64-dim dot product and writes pred_mask + label.
//    Thread 0 writes the sparsity scalar (g_nnz final after insert_kernel).
// ---------------------------------------------------------------------------
__global__ void resolve_kernel(const int*   __restrict__ idx_user,
                               const int*   __restrict__ item_sets,
                               const float* __restrict__ ratings,
                               const float* __restrict__ embed_user,
                               const float* __restrict__ embed_item,
                               float* __restrict__ out) {
    int j = blockIdx.x * blockDim.x + threadIdx.x;
    if (j == 0) {
        double total = (double)NUM_USER * (double)NUM_ITEM;
        out[2ull * NUM_USER * NUM_ITEM] = (float)(total / (double)g_nnz);
    }
    if (j >= NJ) return;

    int b = j / SETLEN;
    unsigned int u    = (unsigned int)idx_user[b];
    unsigned int it   = (unsigned int)item_sets[j];
    unsigned int cell = u * NUM_ITEM + it;

    unsigned long long keyhi = ((unsigned long long)(cell + 1u)) << 17;
    unsigned int h = hash_cell(cell);
    unsigned long long cur;
    while (((cur = g_hash[h]) & ~IDX_MASK) != keyhi) h = (h + 1u) & HASH_MASK;

    if ((unsigned int)(cur & IDX_MASK) != (unsigned int)j) return;  // not the winner

    // 64-dim dot product, float4-vectorized (rows are 256B, 16B-aligned)
    const float4* ur = (const float4*)(embed_user + (size_t)u  * NUM_HIDDEN);
    const float4* ir = (const float4*)(embed_item + (size_t)it * NUM_HIDDEN);
    float acc = 0.0f;
#pragma unroll
    for (int k = 0; k < NUM_HIDDEN / 4; k++) {
        float4 a = ur[k];
        float4 c = ir[k];
        acc = fmaf(a.x, c.x, acc);
        acc = fmaf(a.y, c.y, acc);
        acc = fmaf(a.z, c.z, acc);
        acc = fmaf(a.w, c.w, acc);
    }

    out[cell] = acc;                                           // pred_mask
    out[(size_t)NUM_USER * NUM_ITEM + cell] = ratings[j];      // label
}

// ---------------------------------------------------------------------------
extern "C" void kernel_launch(void* const* d_in, const int* in_sizes, int n_in,
                              void* d_out, int out_size) {
    const int*   idx_user   = (const int*)  d_in[0];
    const int*   item_sets  = (const int*)  d_in[1];
    const float* rating     = (const float*)d_in[2];
    const float* embed_user = (const float*)d_in[3];
    const float* embed_item = (const float*)d_in[4];
    float* out = (float*)d_out;

    // Clear hash + insert keys (tiny) ...
    clear_kernel<<<(HASH_SIZE + 255) / 256, 256>>>();
    insert_kernel<<<(NJ + 255) / 256, 256>>>(idx_user, item_sets);

    // ... zero both 256MB output planes (the HBM-write floor, ~75us) ...
    cudaMemsetAsync(out, 0, 2ull * NUM_USER * NUM_ITEM * sizeof(float), 0);

    // ... then scatter winners + sparsity.
    resolve_kernel<<<(NJ + 255) / 256, 256>>>(idx_user, item_sets, rating,
                                              embed_user, embed_item, out);
}